// round 3
// baseline (speedup 1.0000x reference)
#include <cuda_runtime.h>

#define T_LEN 128
#define B_SZ  512
#define D_IN  768

// ---------------- scratch (device globals; no allocation allowed) ----------
__device__ float g_G [T_LEN * B_SZ * 64];   // bi-LSTM gate preacts (input part + bias)
__device__ float g_h [T_LEN * B_SZ * 16];   // concat bi-LSTM hidden
__device__ float g_Gp[T_LEN * B_SZ * 64];   // ptr-LSTM gate preacts (input part + bias)
__device__ float g_z [T_LEN * B_SZ * 16];   // ptr-LSTM hidden

// ---------------- helpers ---------------------------------------------------
static __device__ __forceinline__ unsigned long long f2u(float2 v) {
    union { float2 f; unsigned long long u; } x; x.f = v; return x.u;
}
static __device__ __forceinline__ float2 u2f(unsigned long long u) {
    union { float2 f; unsigned long long u; } x; x.u = u; return x.f;
}
// packed fp32x2 FMA (B300 FFMA2 — 2x fp32 FMA throughput vs 3-reg FFMA)
static __device__ __forceinline__ float2 ffma2(float2 a, float2 b, float2 c) {
    unsigned long long d;
    asm("fma.rn.f32x2 %0, %1, %2, %3;"
        : "=l"(d) : "l"(f2u(a)), "l"(f2u(b)), "l"(f2u(c)));
    return u2f(d);
}
static __device__ __forceinline__ float2 flo(float4 v) { return make_float2(v.x, v.y); }
static __device__ __forceinline__ float2 fhi(float4 v) { return make_float2(v.z, v.w); }

static __device__ __forceinline__ float sigf(float x) {
    return 1.0f / (1.0f + __expf(-x));
}
static __device__ __forceinline__ float tanh_fast(float x) {
    // 1 - 2/(e^{2x}+1); abs err ~1e-7, handles +-inf saturation correctly
    return 1.0f - 2.0f / (__expf(2.0f * x) + 1.0f);
}

// ---------------- K1: x @ [Wih_f;Wih_b]^T + bias -> g_G ---------------------
// M=65536, N=64, K=768. Tile 128x64, K-chunk 32. f32x2 even/odd-k accumulators.
__global__ void __launch_bounds__(256) k1_gemm(
    const float* __restrict__ x,
    const float* __restrict__ Wf, const float* __restrict__ Wb,
    const float* __restrict__ bihf, const float* __restrict__ bhhf,
    const float* __restrict__ bihb, const float* __restrict__ bhhb)
{
    __shared__ float2 xs2[16][129];  // [k-pair][m]   (pad -> store conflicts ~2-way)
    __shared__ float2 wst[16][65];   // [k-pair][n]   (compute reads conflict-free)

    const int tid = threadIdx.x;
    const int tx = tid & 15;         // 16 column groups (n = tx + 16j)
    const int ty = tid >> 4;         // 16 row groups   (m = ty*8 + i)
    const int rowBase = blockIdx.x * 128;

    float2 acc[8][4];
#pragma unroll
    for (int i = 0; i < 8; i++)
#pragma unroll
        for (int j = 0; j < 4; j++) acc[i][j] = make_float2(0.f, 0.f);

    for (int kc = 0; kc < 24; kc++) {
        const int k0 = kc * 32;
        __syncthreads();
#pragma unroll
        for (int i = 0; i < 4; i++) {
            int idx = tid + i * 256;          // 1024 float4 of x tile
            int m = idx >> 3, kq = idx & 7;
            float4 v = *(const float4*)(x + (size_t)(rowBase + m) * D_IN + k0 + kq * 4);
            xs2[2 * kq][m]     = make_float2(v.x, v.y);
            xs2[2 * kq + 1][m] = make_float2(v.z, v.w);
        }
#pragma unroll
        for (int i = 0; i < 2; i++) {
            int idx = tid + i * 256;          // 512 float4 of W tile
            int n = idx >> 3, kq = idx & 7;
            const float* Wrow = (n < 32) ? (Wf + n * D_IN) : (Wb + (n - 32) * D_IN);
            float4 v = *(const float4*)(Wrow + k0 + kq * 4);
            wst[2 * kq][n]     = make_float2(v.x, v.y);
            wst[2 * kq + 1][n] = make_float2(v.z, v.w);
        }
        __syncthreads();
#pragma unroll
        for (int kk = 0; kk < 16; kk++) {
            float2 a[8], w[4];
#pragma unroll
            for (int i = 0; i < 8; i++) a[i] = xs2[kk][ty * 8 + i];   // 2-addr broadcast
#pragma unroll
            for (int j = 0; j < 4; j++) w[j] = wst[kk][tx + 16 * j];  // conflict-free
#pragma unroll
            for (int i = 0; i < 8; i++)
#pragma unroll
                for (int j = 0; j < 4; j++)
                    acc[i][j] = ffma2(a[i], w[j], acc[i][j]);
        }
    }

    float bias[4];
#pragma unroll
    for (int j = 0; j < 4; j++) {
        int n = tx + 16 * j;
        bias[j] = (n < 32) ? (bihf[n] + bhhf[n]) : (bihb[n - 32] + bhhb[n - 32]);
    }
#pragma unroll
    for (int i = 0; i < 8; i++) {
        float* gp = g_G + (size_t)(rowBase + ty * 8 + i) * 64;
#pragma unroll
        for (int j = 0; j < 4; j++)
            gp[tx + 16 * j] = acc[i][j].x + acc[i][j].y + bias[j];
    }
}

// ---------------- K2: bi-LSTM scans (both directions) -----------------------
// warp = 4 batch elems x 8 hidden units; h broadcast via shfl; gates prefetched.
__global__ void __launch_bounds__(256) k2_bilstm(
    const float* __restrict__ Whhf, const float* __restrict__ Whhb)
{
    const int warpId = (blockIdx.x << 3) + (threadIdx.x >> 5);  // 0..255
    const int lane = threadIdx.x & 31;
    const int dir = warpId >> 7;          // 0=fwd, 1=bwd
    const int wd = warpId & 127;
    const int b = (wd << 2) + (lane >> 3);
    const int j = lane & 7;
    const int srcBase = lane & 0x18;

    const float* Whh = dir ? Whhb : Whhf;
    float wr[4][8];
#pragma unroll
    for (int g = 0; g < 4; g++)
#pragma unroll
        for (int k = 0; k < 8; k++)
            wr[g][k] = Whh[(g * 8 + j) * 8 + k];

    const int t0 = dir ? 127 : 0;
    const long long stepG = dir ? -(long long)(B_SZ * 64) : (long long)(B_SZ * 64);
    const long long stepH = dir ? -(long long)(B_SZ * 16) : (long long)(B_SZ * 16);
    const float* gp = g_G + (size_t)(t0 * B_SZ + b) * 64 + dir * 32 + j;
    float*       hp = g_h + (size_t)(t0 * B_SZ + b) * 16 + dir * 8 + j;

    float h = 0.f, c = 0.f;
    float n0 = gp[0], n1 = gp[8], n2 = gp[16], n3 = gp[24];
    for (int t = 0; t < 128; t++) {
        float q0 = n0, q1 = n1, q2 = n2, q3 = n3;
        if (t < 127) { gp += stepG; n0 = gp[0]; n1 = gp[8]; n2 = gp[16]; n3 = gp[24]; }
        float a0 = 0.f, a1 = 0.f, a2 = 0.f, a3 = 0.f;
#pragma unroll
        for (int k = 0; k < 8; k++) {
            float hk = __shfl_sync(0xffffffffu, h, srcBase + k);
            a0 += wr[0][k] * hk; a1 += wr[1][k] * hk;
            a2 += wr[2][k] * hk; a3 += wr[3][k] * hk;
        }
        float ii = sigf(q0 + a0), ff = sigf(q1 + a1);
        float gg = tanh_fast(q2 + a2), oo = sigf(q3 + a3);
        c = ff * c + ii * gg;
        h = oo * tanh_fast(c);
        *hp = h; hp += stepH;
    }
}

// ---------------- K4: ptr-LSTM input projection h @ Wih_p^T + bias ----------
__global__ void __launch_bounds__(256) k4_proj(
    const float* __restrict__ Wp, const float* __restrict__ bihp,
    const float* __restrict__ bhhp)
{
    __shared__ float4 ws4[64][4];
    __shared__ float bs[64];
    const int tid = threadIdx.x;
    if (tid < 64) bs[tid] = bihp[tid] + bhhp[tid];
    {
        float4 v = ((const float4*)Wp)[tid];   // 256 float4 = 64x16
        ws4[tid >> 2][tid & 3] = v;
    }
    __syncthreads();

    const int m = blockIdx.x * 256 + tid;
    const float4* hv = (const float4*)(g_h + (size_t)m * 16);
    float4 h0 = hv[0], h1 = hv[1], h2 = hv[2], h3 = hv[3];
    float* gp = g_Gp + (size_t)m * 64;
#pragma unroll
    for (int n4 = 0; n4 < 16; n4++) {
        float4 o;
        float* op = &o.x;
#pragma unroll
        for (int q = 0; q < 4; q++) {
            int n = n4 * 4 + q;
            float4 w0 = ws4[n][0], w1 = ws4[n][1], w2 = ws4[n][2], w3 = ws4[n][3];
            float s = bs[n];
            s += h0.x * w0.x + h0.y * w0.y + h0.z * w0.z + h0.w * w0.w;
            s += h1.x * w1.x + h1.y * w1.y + h1.z * w1.z + h1.w * w1.w;
            s += h2.x * w2.x + h2.y * w2.y + h2.z * w2.z + h2.w * w2.w;
            s += h3.x * w3.x + h3.y * w3.y + h3.z * w3.z + h3.w * w3.w;
            op[q] = s;
        }
        ((float4*)gp)[n4] = o;
    }
}

// ---------------- K5: ptr-LSTM scan (H=16) ----------------------------------
// warp = 2 batch elems x 16 hidden units.
__global__ void __launch_bounds__(256) k5_ptr(const float* __restrict__ Whhp)
{
    const int warpId = (blockIdx.x << 3) + (threadIdx.x >> 5);  // 0..255
    const int lane = threadIdx.x & 31;
    const int b = (warpId << 1) + (lane >> 4);
    const int j = lane & 15;
    const int srcBase = lane & 16;

    float wr[4][16];
#pragma unroll
    for (int g = 0; g < 4; g++)
#pragma unroll
        for (int k = 0; k < 16; k++)
            wr[g][k] = Whhp[(g * 16 + j) * 16 + k];

    const float* gp = g_Gp + (size_t)b * 64 + j;
    float*       zp = g_z  + (size_t)b * 16 + j;
    float h = 0.f, c = 0.f;
    float n0 = gp[0], n1 = gp[16], n2 = gp[32], n3 = gp[48];
    for (int t = 0; t < 128; t++) {
        float q0 = n0, q1 = n1, q2 = n2, q3 = n3;
        if (t < 127) {
            gp += B_SZ * 64;
            n0 = gp[0]; n1 = gp[16]; n2 = gp[32]; n3 = gp[48];
        }
        float a0 = 0.f, a1 = 0.f, a2 = 0.f, a3 = 0.f;
#pragma unroll
        for (int k = 0; k < 16; k++) {
            float hk = __shfl_sync(0xffffffffu, h, srcBase + k);
            a0 += wr[0][k] * hk; a1 += wr[1][k] * hk;
            a2 += wr[2][k] * hk; a3 += wr[3][k] * hk;
        }
        float ii = sigf(q0 + a0), ff = sigf(q1 + a1);
        float gg = tanh_fast(q2 + a2), oo = sigf(q3 + a3);
        c = ff * c + ii * gg;
        h = oo * tanh_fast(c);
        *zp = h; zp += B_SZ * 16;
    }
}

// ---------------- K6: attention + context + scoring epilogue ----------------
// One block per t. S[b,c] = h_b . z_c ; softmax over b (columns); ctx then score.
// |S| < 16 guaranteed (h,z tanh-bounded), so exp without max-subtraction is
// exact-equivalent to the reference softmax and fp32-safe.
__global__ void __launch_bounds__(512) k6_attn(
    const float* __restrict__ Wh, const float* __restrict__ We,
    const float* __restrict__ Wv, float* __restrict__ out)
{
    extern __shared__ float sm[];
    float* hs  = sm;              // 8192
    float* zs  = sm + 8192;       // 8192
    float* rcs = sm + 16384;      // 512
    float* whs = sm + 16896;      // 256
    float* wes = sm + 17152;      // 256
    float* wvs = sm + 17408;      // 16

    const int t = blockIdx.x;
    const int tid = threadIdx.x;

    float4* hs4 = (float4*)hs;
    float4* zs4 = (float4*)zs;
    {
        const float4* hg = (const float4*)(g_h + (size_t)t * B_SZ * 16);
        const float4* zg = (const float4*)(g_z + (size_t)t * B_SZ * 16);
#pragma unroll
        for (int i = 0; i < 4; i++) {
            hs4[tid + i * 512] = hg[tid + i * 512];
            zs4[tid + i * 512] = zg[tid + i * 512];
        }
    }
    if (tid < 256) { whs[tid] = Wh[tid]; wes[tid] = We[tid]; }
    if (tid < 16)  wvs[tid] = Wv[tid];
    __syncthreads();

    // ---- pass A: column sums of exp(S[:,c]), c = tid ----
    {
        const float4* zc = zs4 + tid * 4;
        float4 z0 = zc[0], z1 = zc[1], z2 = zc[2], z3 = zc[3];
        float colsum = 0.f;
        const float4* hp = hs4;
#pragma unroll 4
        for (int b = 0; b < 512; b++) {
            float4 h0 = hp[0], h1 = hp[1], h2 = hp[2], h3 = hp[3];
            hp += 4;
            float2 s2 = make_float2(0.f, 0.f);
            s2 = ffma2(flo(h0), flo(z0), s2); s2 = ffma2(fhi(h0), fhi(z0), s2);
            s2 = ffma2(flo(h1), flo(z1), s2); s2 = ffma2(fhi(h1), fhi(z1), s2);
            s2 = ffma2(flo(h2), flo(z2), s2); s2 = ffma2(fhi(h2), fhi(z2), s2);
            s2 = ffma2(flo(h3), flo(z3), s2); s2 = ffma2(fhi(h3), fhi(z3), s2);
            colsum += __expf(s2.x + s2.y);
        }
        rcs[tid] = 1.0f / colsum;
    }
    __syncthreads();

    // ---- pass B: rows b = tid; recompute S, weight, accumulate ctx ----
    {
        const float4* hb = hs4 + tid * 4;
        float4 b0 = hb[0], b1 = hb[1], b2 = hb[2], b3 = hb[3];
        float2 ctx[8];
#pragma unroll
        for (int q = 0; q < 8; q++) ctx[q] = make_float2(0.f, 0.f);

#pragma unroll 2
        for (int cc = 0; cc < 512; cc++) {
            float4 z0 = zs4[cc * 4 + 0], z1 = zs4[cc * 4 + 1];
            float4 z2 = zs4[cc * 4 + 2], z3 = zs4[cc * 4 + 3];
            float4 h0 = hs4[cc * 4 + 0], h1 = hs4[cc * 4 + 1];
            float4 h2 = hs4[cc * 4 + 2], h3 = hs4[cc * 4 + 3];
            float2 s2 = make_float2(0.f, 0.f);
            s2 = ffma2(flo(b0), flo(z0), s2); s2 = ffma2(fhi(b0), fhi(z0), s2);
            s2 = ffma2(flo(b1), flo(z1), s2); s2 = ffma2(fhi(b1), fhi(z1), s2);
            s2 = ffma2(flo(b2), flo(z2), s2); s2 = ffma2(fhi(b2), fhi(z2), s2);
            s2 = ffma2(flo(b3), flo(z3), s2); s2 = ffma2(fhi(b3), fhi(z3), s2);
            float w = __expf(s2.x + s2.y) * rcs[cc];
            float2 w2 = make_float2(w, w);
            ctx[0] = ffma2(w2, flo(h0), ctx[0]); ctx[1] = ffma2(w2, fhi(h0), ctx[1]);
            ctx[2] = ffma2(w2, flo(h1), ctx[2]); ctx[3] = ffma2(w2, fhi(h1), ctx[3]);
            ctx[4] = ffma2(w2, flo(h2), ctx[4]); ctx[5] = ffma2(w2, fhi(h2), ctx[5]);
            ctx[6] = ffma2(w2, flo(h3), ctx[6]); ctx[7] = ffma2(w2, fhi(h3), ctx[7]);
        }

        // scoring epilogue: p = sigmoid( W_v . tanh(h W_h^T + ctx W_e^T) )
        float hv[16], cv[16];
        const float* bp = &b0.x;   // b0..b3 contiguous? copy explicitly instead:
        hv[0]=b0.x; hv[1]=b0.y; hv[2]=b0.z; hv[3]=b0.w;
        hv[4]=b1.x; hv[5]=b1.y; hv[6]=b1.z; hv[7]=b1.w;
        hv[8]=b2.x; hv[9]=b2.y; hv[10]=b2.z; hv[11]=b2.w;
        hv[12]=b3.x; hv[13]=b3.y; hv[14]=b3.z; hv[15]=b3.w;
        (void)bp;
#pragma unroll
        for (int q = 0; q < 8; q++) { cv[2*q] = ctx[q].x; cv[2*q+1] = ctx[q].y; }

        float pacc = 0.f;
#pragma unroll
        for (int d = 0; d < 16; d++) {
            float s = 0.f;
#pragma unroll
            for (int k = 0; k < 16; k++)
                s += hv[k] * whs[d * 16 + k] + cv[k] * wes[d * 16 + k];
            pacc += tanh_fast(s) * wvs[d];
        }
        out[t * B_SZ + tid] = sigf(pacc);
    }
}

// ---------------- launch -----------------------------------------------------
extern "C" void kernel_launch(void* const* d_in, const int* in_sizes, int n_in,
                              void* d_out, int out_size)
{
    const float* x    = (const float*)d_in[0];
    const float* Wihf = (const float*)d_in[1];
    const float* Whhf = (const float*)d_in[2];
    const float* bihf = (const float*)d_in[3];
    const float* bhhf = (const float*)d_in[4];
    const float* Wihb = (const float*)d_in[5];
    const float* Whhb = (const float*)d_in[6];
    const float* bihb = (const float*)d_in[7];
    const float* bhhb = (const float*)d_in[8];
    const float* Wihp = (const float*)d_in[9];
    const float* Whhp = (const float*)d_in[10];
    const float* bihp = (const float*)d_in[11];
    const float* bhhp = (const float*)d_in[12];
    const float* Wh   = (const float*)d_in[13];
    const float* We   = (const float*)d_in[14];
    const float* Wv   = (const float*)d_in[15];
    float* out = (float*)d_out;

    k1_gemm<<<512, 256>>>(x, Wihf, Wihb, bihf, bhhf, bihb, bhhb);
    k2_bilstm<<<32, 256>>>(Whhf, Whhb);
    k4_proj<<<256, 256>>>(Wihp, bihp, bhhp);
    k5_ptr<<<32, 256>>>(Whhp);

    const int smemK6 = (8192 + 8192 + 512 + 256 + 256 + 16) * 4;  // 69696 B
    cudaFuncSetAttribute(k6_attn, cudaFuncAttributeMaxDynamicSharedMemorySize, smemK6);
    k6_attn<<<128, 512, smemK6>>>(Wh, We, Wv, out);
}

// round 4
// speedup vs baseline: 1.0690x; 1.0690x over previous
#include <cuda_runtime.h>

#define T_LEN 128
#define B_SZ  512
#define D_IN  768

// ---------------- scratch (device globals; no allocation allowed) ----------
__device__ float g_G [T_LEN * B_SZ * 64];   // bi-LSTM gate preacts (input part + bias)
__device__ float g_h [T_LEN * B_SZ * 16];   // concat bi-LSTM hidden
__device__ float g_Gp[T_LEN * B_SZ * 64];   // ptr-LSTM gate preacts (input part + bias)
__device__ float g_z [T_LEN * B_SZ * 16];   // ptr-LSTM hidden

// ---------------- helpers ---------------------------------------------------
static __device__ __forceinline__ unsigned long long f2u(float2 v) {
    union { float2 f; unsigned long long u; } x; x.f = v; return x.u;
}
static __device__ __forceinline__ float2 u2f(unsigned long long u) {
    union { float2 f; unsigned long long u; } x; x.u = u; return x.f;
}
// packed fp32x2 FMA (B300 FFMA2 — 2x fp32 FMA throughput vs 3-reg FFMA)
static __device__ __forceinline__ float2 ffma2(float2 a, float2 b, float2 c) {
    unsigned long long d;
    asm("fma.rn.f32x2 %0, %1, %2, %3;"
        : "=l"(d) : "l"(f2u(a)), "l"(f2u(b)), "l"(f2u(c)));
    return u2f(d);
}
static __device__ __forceinline__ float2 flo(float4 v) { return make_float2(v.x, v.y); }
static __device__ __forceinline__ float2 fhi(float4 v) { return make_float2(v.z, v.w); }

static __device__ __forceinline__ float sigf(float x) {
    return 1.0f / (1.0f + __expf(-x));
}
static __device__ __forceinline__ float tanh_fast(float x) {
    // 1 - 2/(e^{2x}+1); abs err ~1e-7, handles +-inf saturation correctly
    return 1.0f - 2.0f / (__expf(2.0f * x) + 1.0f);
}

// ---------------- K1: x @ [Wih_f;Wih_b]^T + bias -> g_G ---------------------
// M=65536, N=64, K=768. Tile 128x64, K-chunk 32. f32x2 even/odd-k accumulators.
__global__ void __launch_bounds__(256) k1_gemm(
    const float* __restrict__ x,
    const float* __restrict__ Wf, const float* __restrict__ Wb,
    const float* __restrict__ bihf, const float* __restrict__ bhhf,
    const float* __restrict__ bihb, const float* __restrict__ bhhb)
{
    __shared__ float2 xs2[16][129];  // [k-pair][m]
    __shared__ float2 wst[16][65];   // [k-pair][n]

    const int tid = threadIdx.x;
    const int tx = tid & 15;         // 16 column groups (n = tx + 16j)
    const int ty = tid >> 4;         // 16 row groups   (m = ty*8 + i)
    const int rowBase = blockIdx.x * 128;

    float2 acc[8][4];
#pragma unroll
    for (int i = 0; i < 8; i++)
#pragma unroll
        for (int j = 0; j < 4; j++) acc[i][j] = make_float2(0.f, 0.f);

    for (int kc = 0; kc < 24; kc++) {
        const int k0 = kc * 32;
        __syncthreads();
#pragma unroll
        for (int i = 0; i < 4; i++) {
            int idx = tid + i * 256;          // 1024 float4 of x tile
            int m = idx >> 3, kq = idx & 7;
            float4 v = *(const float4*)(x + (size_t)(rowBase + m) * D_IN + k0 + kq * 4);
            xs2[2 * kq][m]     = make_float2(v.x, v.y);
            xs2[2 * kq + 1][m] = make_float2(v.z, v.w);
        }
#pragma unroll
        for (int i = 0; i < 2; i++) {
            int idx = tid + i * 256;          // 512 float4 of W tile
            int n = idx >> 3, kq = idx & 7;
            const float* Wrow = (n < 32) ? (Wf + n * D_IN) : (Wb + (n - 32) * D_IN);
            float4 v = *(const float4*)(Wrow + k0 + kq * 4);
            wst[2 * kq][n]     = make_float2(v.x, v.y);
            wst[2 * kq + 1][n] = make_float2(v.z, v.w);
        }
        __syncthreads();
#pragma unroll
        for (int kk = 0; kk < 16; kk++) {
            float2 a[8], w[4];
#pragma unroll
            for (int i = 0; i < 8; i++) a[i] = xs2[kk][ty * 8 + i];
#pragma unroll
            for (int j = 0; j < 4; j++) w[j] = wst[kk][tx + 16 * j];
#pragma unroll
            for (int i = 0; i < 8; i++)
#pragma unroll
                for (int j = 0; j < 4; j++)
                    acc[i][j] = ffma2(a[i], w[j], acc[i][j]);
        }
    }

    float bias[4];
#pragma unroll
    for (int j = 0; j < 4; j++) {
        int n = tx + 16 * j;
        bias[j] = (n < 32) ? (bihf[n] + bhhf[n]) : (bihb[n - 32] + bhhb[n - 32]);
    }
#pragma unroll
    for (int i = 0; i < 8; i++) {
        float* gp = g_G + (size_t)(rowBase + ty * 8 + i) * 64;
#pragma unroll
        for (int j = 0; j < 4; j++)
            gp[tx + 16 * j] = acc[i][j].x + acc[i][j].y + bias[j];
    }
}

// ---------------- K2: bi-LSTM scans (both directions) -----------------------
// ONE WARP PER BLOCK (256 blocks -> ~1 warp/SMSP chip-wide) + prefetch depth 4
// so the ~577-cycle DRAM latency of the streamed gate reads is fully hidden.
// warp = 4 batch elems x 8 hidden units; h broadcast via shfl.
__global__ void __launch_bounds__(32) k2_bilstm(
    const float* __restrict__ Whhf, const float* __restrict__ Whhb)
{
    const int warpId = blockIdx.x;        // 0..255
    const int lane = threadIdx.x & 31;
    const int dir = warpId >> 7;          // 0=fwd, 1=bwd
    const int wd = warpId & 127;
    const int b = (wd << 2) + (lane >> 3);
    const int j = lane & 7;
    const int srcBase = lane & 0x18;

    const float* Whh = dir ? Whhb : Whhf;
    float wr[4][8];
#pragma unroll
    for (int g = 0; g < 4; g++)
#pragma unroll
        for (int k = 0; k < 8; k++)
            wr[g][k] = Whh[(g * 8 + j) * 8 + k];

    const int t0 = dir ? 127 : 0;
    const long long stepG = dir ? -(long long)(B_SZ * 64) : (long long)(B_SZ * 64);
    const long long stepH = dir ? -(long long)(B_SZ * 16) : (long long)(B_SZ * 16);
    const float* gp0 = g_G + (size_t)(t0 * B_SZ + b) * 64 + dir * 32 + j;
    float*       hp  = g_h + (size_t)(t0 * B_SZ + b) * 16 + dir * 8 + j;

    // prefetch depth 4 cyclic buffer
    float nb[4][4];
#pragma unroll
    for (int p = 0; p < 4; p++) {
        const float* q = gp0 + (long long)p * stepG;
        nb[p][0] = q[0]; nb[p][1] = q[8]; nb[p][2] = q[16]; nb[p][3] = q[24];
    }
    const float* gpf = gp0 + 4 * stepG;   // next address to prefetch

    float h = 0.f, c = 0.f;
    for (int tt = 0; tt < 128; tt += 4) {
#pragma unroll
        for (int p = 0; p < 4; p++) {
            const int s = tt + p;
            float q0 = nb[p][0], q1 = nb[p][1], q2 = nb[p][2], q3 = nb[p][3];
            if (s < 124) {
                nb[p][0] = gpf[0]; nb[p][1] = gpf[8];
                nb[p][2] = gpf[16]; nb[p][3] = gpf[24];
            }
            gpf += stepG;
            float a0 = 0.f, a1 = 0.f, a2 = 0.f, a3 = 0.f;
#pragma unroll
            for (int k = 0; k < 8; k++) {
                float hk = __shfl_sync(0xffffffffu, h, srcBase + k);
                a0 += wr[0][k] * hk; a1 += wr[1][k] * hk;
                a2 += wr[2][k] * hk; a3 += wr[3][k] * hk;
            }
            float ii = sigf(q0 + a0), ff = sigf(q1 + a1);
            float gg = tanh_fast(q2 + a2), oo = sigf(q3 + a3);
            c = ff * c + ii * gg;
            h = oo * tanh_fast(c);
            *hp = h; hp += stepH;
        }
    }
}

// ---------------- K4: ptr-LSTM input projection h @ Wih_p^T + bias ----------
__global__ void __launch_bounds__(256) k4_proj(
    const float* __restrict__ Wp, const float* __restrict__ bihp,
    const float* __restrict__ bhhp)
{
    __shared__ float4 ws4[64][4];
    __shared__ float bs[64];
    const int tid = threadIdx.x;
    if (tid < 64) bs[tid] = bihp[tid] + bhhp[tid];
    {
        float4 v = ((const float4*)Wp)[tid];   // 256 float4 = 64x16
        ws4[tid >> 2][tid & 3] = v;
    }
    __syncthreads();

    const int m = blockIdx.x * 256 + tid;
    const float4* hv = (const float4*)(g_h + (size_t)m * 16);
    float4 h0 = hv[0], h1 = hv[1], h2 = hv[2], h3 = hv[3];
    float* gp = g_Gp + (size_t)m * 64;
#pragma unroll
    for (int n4 = 0; n4 < 16; n4++) {
        float4 o;
        float* op = &o.x;
#pragma unroll
        for (int q = 0; q < 4; q++) {
            int n = n4 * 4 + q;
            float4 w0 = ws4[n][0], w1 = ws4[n][1], w2 = ws4[n][2], w3 = ws4[n][3];
            float s = bs[n];
            s += h0.x * w0.x + h0.y * w0.y + h0.z * w0.z + h0.w * w0.w;
            s += h1.x * w1.x + h1.y * w1.y + h1.z * w1.z + h1.w * w1.w;
            s += h2.x * w2.x + h2.y * w2.y + h2.z * w2.z + h2.w * w2.w;
            s += h3.x * w3.x + h3.y * w3.y + h3.z * w3.z + h3.w * w3.w;
            op[q] = s;
        }
        ((float4*)gp)[n4] = o;
    }
}

// ---------------- K5: ptr-LSTM scan (H=16) ----------------------------------
// ONE WARP PER BLOCK + prefetch depth 4 (same rationale as k2).
// warp = 2 batch elems x 16 hidden units.
__global__ void __launch_bounds__(32) k5_ptr(const float* __restrict__ Whhp)
{
    const int warpId = blockIdx.x;        // 0..255
    const int lane = threadIdx.x & 31;
    const int b = (warpId << 1) + (lane >> 4);
    const int j = lane & 15;
    const int srcBase = lane & 16;

    float wr[4][16];
#pragma unroll
    for (int g = 0; g < 4; g++)
#pragma unroll
        for (int k = 0; k < 16; k++)
            wr[g][k] = Whhp[(g * 16 + j) * 16 + k];

    const float* gp0 = g_Gp + (size_t)b * 64 + j;
    float*       zp  = g_z  + (size_t)b * 16 + j;
    const long long stepG = (long long)B_SZ * 64;

    float nb[4][4];
#pragma unroll
    for (int p = 0; p < 4; p++) {
        const float* q = gp0 + (long long)p * stepG;
        nb[p][0] = q[0]; nb[p][1] = q[16]; nb[p][2] = q[32]; nb[p][3] = q[48];
    }
    const float* gpf = gp0 + 4 * stepG;

    float h = 0.f, c = 0.f;
    for (int tt = 0; tt < 128; tt += 4) {
#pragma unroll
        for (int p = 0; p < 4; p++) {
            const int s = tt + p;
            float q0 = nb[p][0], q1 = nb[p][1], q2 = nb[p][2], q3 = nb[p][3];
            if (s < 124) {
                nb[p][0] = gpf[0];  nb[p][1] = gpf[16];
                nb[p][2] = gpf[32]; nb[p][3] = gpf[48];
            }
            gpf += stepG;
            // split each gate's dot into 2 halves -> shorter FMA dependency chains
            float a0 = 0.f, a1 = 0.f, a2 = 0.f, a3 = 0.f;
            float b0 = 0.f, b1 = 0.f, b2 = 0.f, b3 = 0.f;
#pragma unroll
            for (int k = 0; k < 8; k++) {
                float hk = __shfl_sync(0xffffffffu, h, srcBase + k);
                a0 += wr[0][k] * hk; a1 += wr[1][k] * hk;
                a2 += wr[2][k] * hk; a3 += wr[3][k] * hk;
            }
#pragma unroll
            for (int k = 8; k < 16; k++) {
                float hk = __shfl_sync(0xffffffffu, h, srcBase + k);
                b0 += wr[0][k] * hk; b1 += wr[1][k] * hk;
                b2 += wr[2][k] * hk; b3 += wr[3][k] * hk;
            }
            float ii = sigf(q0 + a0 + b0), ff = sigf(q1 + a1 + b1);
            float gg = tanh_fast(q2 + a2 + b2), oo = sigf(q3 + a3 + b3);
            c = ff * c + ii * gg;
            h = oo * tanh_fast(c);
            *zp = h; zp += B_SZ * 16;
        }
    }
}

// ---------------- K6: attention + context + scoring epilogue ----------------
// One block per t. S[b,c] = h_b . z_c ; softmax over b (columns); ctx then score.
// |S| < 16 guaranteed (h,z tanh-bounded), so exp without max-subtraction is
// exact-equivalent to the reference softmax and fp32-safe.
__global__ void __launch_bounds__(512) k6_attn(
    const float* __restrict__ Wh, const float* __restrict__ We,
    const float* __restrict__ Wv, float* __restrict__ out)
{
    extern __shared__ float sm[];
    float* hs  = sm;              // 8192
    float* zs  = sm + 8192;       // 8192
    float* rcs = sm + 16384;      // 512
    float* whs = sm + 16896;      // 256
    float* wes = sm + 17152;      // 256
    float* wvs = sm + 17408;      // 16

    const int t = blockIdx.x;
    const int tid = threadIdx.x;

    float4* hs4 = (float4*)hs;
    float4* zs4 = (float4*)zs;
    {
        const float4* hg = (const float4*)(g_h + (size_t)t * B_SZ * 16);
        const float4* zg = (const float4*)(g_z + (size_t)t * B_SZ * 16);
#pragma unroll
        for (int i = 0; i < 4; i++) {
            hs4[tid + i * 512] = hg[tid + i * 512];
            zs4[tid + i * 512] = zg[tid + i * 512];
        }
    }
    if (tid < 256) { whs[tid] = Wh[tid]; wes[tid] = We[tid]; }
    if (tid < 16)  wvs[tid] = Wv[tid];
    __syncthreads();

    // ---- pass A: column sums of exp(S[:,c]), c = tid ----
    {
        const float4* zc = zs4 + tid * 4;
        float4 z0 = zc[0], z1 = zc[1], z2 = zc[2], z3 = zc[3];
        float colsum = 0.f;
        const float4* hp = hs4;
#pragma unroll 4
        for (int b = 0; b < 512; b++) {
            float4 h0 = hp[0], h1 = hp[1], h2 = hp[2], h3 = hp[3];
            hp += 4;
            float2 s2 = make_float2(0.f, 0.f);
            s2 = ffma2(flo(h0), flo(z0), s2); s2 = ffma2(fhi(h0), fhi(z0), s2);
            s2 = ffma2(flo(h1), flo(z1), s2); s2 = ffma2(fhi(h1), fhi(z1), s2);
            s2 = ffma2(flo(h2), flo(z2), s2); s2 = ffma2(fhi(h2), fhi(z2), s2);
            s2 = ffma2(flo(h3), flo(z3), s2); s2 = ffma2(fhi(h3), fhi(z3), s2);
            colsum += __expf(s2.x + s2.y);
        }
        rcs[tid] = 1.0f / colsum;
    }
    __syncthreads();

    // ---- pass B: rows b = tid; recompute S, weight, accumulate ctx ----
    {
        const float4* hb = hs4 + tid * 4;
        float4 b0 = hb[0], b1 = hb[1], b2 = hb[2], b3 = hb[3];
        float2 ctx[8];
#pragma unroll
        for (int q = 0; q < 8; q++) ctx[q] = make_float2(0.f, 0.f);

#pragma unroll 2
        for (int cc = 0; cc < 512; cc++) {
            float4 z0 = zs4[cc * 4 + 0], z1 = zs4[cc * 4 + 1];
            float4 z2 = zs4[cc * 4 + 2], z3 = zs4[cc * 4 + 3];
            float4 h0 = hs4[cc * 4 + 0], h1 = hs4[cc * 4 + 1];
            float4 h2 = hs4[cc * 4 + 2], h3 = hs4[cc * 4 + 3];
            float2 s2 = make_float2(0.f, 0.f);
            s2 = ffma2(flo(b0), flo(z0), s2); s2 = ffma2(fhi(b0), fhi(z0), s2);
            s2 = ffma2(flo(b1), flo(z1), s2); s2 = ffma2(fhi(b1), fhi(z1), s2);
            s2 = ffma2(flo(b2), flo(z2), s2); s2 = ffma2(fhi(b2), fhi(z2), s2);
            s2 = ffma2(flo(b3), flo(z3), s2); s2 = ffma2(fhi(b3), fhi(z3), s2);
            float w = __expf(s2.x + s2.y) * rcs[cc];
            float2 w2 = make_float2(w, w);
            ctx[0] = ffma2(w2, flo(h0), ctx[0]); ctx[1] = ffma2(w2, fhi(h0), ctx[1]);
            ctx[2] = ffma2(w2, flo(h1), ctx[2]); ctx[3] = ffma2(w2, fhi(h1), ctx[3]);
            ctx[4] = ffma2(w2, flo(h2), ctx[4]); ctx[5] = ffma2(w2, fhi(h2), ctx[5]);
            ctx[6] = ffma2(w2, flo(h3), ctx[6]); ctx[7] = ffma2(w2, fhi(h3), ctx[7]);
        }

        // scoring epilogue: p = sigmoid( W_v . tanh(h W_h^T + ctx W_e^T) )
        float hv[16], cv[16];
        hv[0]=b0.x; hv[1]=b0.y; hv[2]=b0.z; hv[3]=b0.w;
        hv[4]=b1.x; hv[5]=b1.y; hv[6]=b1.z; hv[7]=b1.w;
        hv[8]=b2.x; hv[9]=b2.y; hv[10]=b2.z; hv[11]=b2.w;
        hv[12]=b3.x; hv[13]=b3.y; hv[14]=b3.z; hv[15]=b3.w;
#pragma unroll
        for (int q = 0; q < 8; q++) { cv[2*q] = ctx[q].x; cv[2*q+1] = ctx[q].y; }

        float pacc = 0.f;
#pragma unroll
        for (int d = 0; d < 16; d++) {
            float s = 0.f;
#pragma unroll
            for (int k = 0; k < 16; k++)
                s += hv[k] * whs[d * 16 + k] + cv[k] * wes[d * 16 + k];
            pacc += tanh_fast(s) * wvs[d];
        }
        out[t * B_SZ + tid] = sigf(pacc);
    }
}

// ---------------- launch -----------------------------------------------------
extern "C" void kernel_launch(void* const* d_in, const int* in_sizes, int n_in,
                              void* d_out, int out_size)
{
    const float* x    = (const float*)d_in[0];
    const float* Wihf = (const float*)d_in[1];
    const float* Whhf = (const float*)d_in[2];
    const float* bihf = (const float*)d_in[3];
    const float* bhhf = (const float*)d_in[4];
    const float* Wihb = (const float*)d_in[5];
    const float* Whhb = (const float*)d_in[6];
    const float* bihb = (const float*)d_in[7];
    const float* bhhb = (const float*)d_in[8];
    const float* Wihp = (const float*)d_in[9];
    const float* Whhp = (const float*)d_in[10];
    const float* bihp = (const float*)d_in[11];
    const float* bhhp = (const float*)d_in[12];
    const float* Wh   = (const float*)d_in[13];
    const float* We   = (const float*)d_in[14];
    const float* Wv   = (const float*)d_in[15];
    float* out = (float*)d_out;

    k1_gemm<<<512, 256>>>(x, Wihf, Wihb, bihf, bhhf, bihb, bhhb);
    k2_bilstm<<<256, 32>>>(Whhf, Whhb);
    k4_proj<<<256, 256>>>(Wihp, bihp, bhhp);
    k5_ptr<<<256, 32>>>(Whhp);

    const int smemK6 = (8192 + 8192 + 512 + 256 + 256 + 16) * 4;  // 69696 B
    cudaFuncSetAttribute(k6_attn, cudaFuncAttributeMaxDynamicSharedMemorySize, smemK6);
    k6_attn<<<128, 512, smemK6>>>(Wh, We, Wv, out);
}

// round 5
// speedup vs baseline: 1.4840x; 1.3881x over previous
#include <cuda_runtime.h>
#include <cuda_bf16.h>

#define T_LEN 128
#define B_SZ  512
#define D_IN  768

// ---------------- scratch (device globals; no allocation allowed) ----------
__device__ float g_G [T_LEN * B_SZ * 64];   // bi-LSTM gate preacts (input part + bias)
__device__ float g_h [T_LEN * B_SZ * 16];   // concat bi-LSTM hidden
__device__ float g_Gp[T_LEN * B_SZ * 64];   // ptr-LSTM gate preacts (input part + bias)
__device__ float g_z [T_LEN * B_SZ * 16];   // ptr-LSTM hidden

// ---------------- helpers ---------------------------------------------------
static __device__ __forceinline__ unsigned long long f2u(float2 v) {
    union { float2 f; unsigned long long u; } x; x.f = v; return x.u;
}
static __device__ __forceinline__ float2 u2f(unsigned long long u) {
    union { float2 f; unsigned long long u; } x; x.u = u; return x.f;
}
// packed fp32x2 FMA (B300 FFMA2 — 2x fp32 FMA throughput vs 3-reg FFMA)
static __device__ __forceinline__ float2 ffma2(float2 a, float2 b, float2 c) {
    unsigned long long d;
    asm("fma.rn.f32x2 %0, %1, %2, %3;"
        : "=l"(d) : "l"(f2u(a)), "l"(f2u(b)), "l"(f2u(c)));
    return u2f(d);
}
static __device__ __forceinline__ float2 flo(float4 v) { return make_float2(v.x, v.y); }
static __device__ __forceinline__ float2 fhi(float4 v) { return make_float2(v.z, v.w); }

static __device__ __forceinline__ float sigf(float x) {
    return 1.0f / (1.0f + __expf(-x));
}
static __device__ __forceinline__ float tanh_fast(float x) {
    return 1.0f - 2.0f / (__expf(2.0f * x) + 1.0f);
}

// pack two floats into bf16x2 hi part and residual lo part
static __device__ __forceinline__ void bf16split2(float a, float b,
                                                  unsigned& hi, unsigned& lo) {
    __nv_bfloat16 ah = __float2bfloat16_rn(a);
    __nv_bfloat16 bh = __float2bfloat16_rn(b);
    float ar = a - __bfloat162float(ah);
    float br = b - __bfloat162float(bh);
    __nv_bfloat16 al = __float2bfloat16_rn(ar);
    __nv_bfloat16 bl = __float2bfloat16_rn(br);
    hi = (unsigned)__bfloat16_as_ushort(ah) | ((unsigned)__bfloat16_as_ushort(bh) << 16);
    lo = (unsigned)__bfloat16_as_ushort(al) | ((unsigned)__bfloat16_as_ushort(bl) << 16);
}

static __device__ __forceinline__ void mma_bf16(float* d, const unsigned* a,
                                                const unsigned* b) {
    asm volatile(
        "mma.sync.aligned.m16n8k16.row.col.f32.bf16.bf16.f32 "
        "{%0,%1,%2,%3}, {%4,%5,%6,%7}, {%8,%9}, {%0,%1,%2,%3};"
        : "+f"(d[0]), "+f"(d[1]), "+f"(d[2]), "+f"(d[3])
        : "r"(a[0]), "r"(a[1]), "r"(a[2]), "r"(a[3]), "r"(b[0]), "r"(b[1]));
}

// ---------------- K1: x @ [Wih_f;Wih_b]^T + bias -> g_G (bf16x3 tensor) -----
// M=65536 (512 blocks x 128 rows), N=64, K=768 (24 chunks of 32).
// Split precision: x = xh + xl, W = wh + wl (bf16); C = xh*wh + xh*wl + xl*wh.
// Block: 128 threads = 4 warps, each warp m32 x n64.
#define K1_PITCH 20   // b32 words per staged row (16 used + 4 pad; conflict-free frags)
__global__ void __launch_bounds__(128) k1_gemm(
    const float* __restrict__ x,
    const float* __restrict__ Wf, const float* __restrict__ Wb,
    const float* __restrict__ bihf, const float* __restrict__ bhhf,
    const float* __restrict__ bihb, const float* __restrict__ bhhb)
{
    __shared__ unsigned sXhi[128 * K1_PITCH];
    __shared__ unsigned sXlo[128 * K1_PITCH];
    __shared__ unsigned sWhi[64 * K1_PITCH];
    __shared__ unsigned sWlo[64 * K1_PITCH];
    __shared__ float    sBias[64];

    const int tid  = threadIdx.x;
    const int warp = tid >> 5;
    const int lane = tid & 31;
    const int g    = lane >> 2;   // 0..7
    const int tig  = lane & 3;    // 0..3
    const int rowBase = blockIdx.x * 128;

    if (tid < 64)
        sBias[tid] = (tid < 32) ? (bihf[tid] + bhhf[tid])
                                : (bihb[tid - 32] + bhhb[tid - 32]);

    float acc[2][8][4];
#pragma unroll
    for (int m = 0; m < 2; m++)
#pragma unroll
        for (int n = 0; n < 8; n++)
#pragma unroll
            for (int q = 0; q < 4; q++) acc[m][n][q] = 0.f;

    for (int kc = 0; kc < 24; kc++) {
        const int k0 = kc * 32;
        __syncthreads();
        // stage X tile: 128 rows x 32 k  (8 float4 per thread)
#pragma unroll
        for (int i = 0; i < 8; i++) {
            int idx = tid + i * 128;
            int row = idx >> 3, kq = idx & 7;
            float4 v = *(const float4*)(x + (size_t)(rowBase + row) * D_IN + k0 + kq * 4);
            unsigned h0, l0, h1, l1;
            bf16split2(v.x, v.y, h0, l0);
            bf16split2(v.z, v.w, h1, l1);
            int base = row * K1_PITCH + 2 * kq;
            sXhi[base] = h0; sXhi[base + 1] = h1;
            sXlo[base] = l0; sXlo[base + 1] = l1;
        }
        // stage W tile: 64 rows x 32 k  (4 float4 per thread)
#pragma unroll
        for (int i = 0; i < 4; i++) {
            int idx = tid + i * 128;
            int n = idx >> 3, kq = idx & 7;
            const float* Wrow = (n < 32) ? (Wf + n * D_IN) : (Wb + (n - 32) * D_IN);
            float4 v = *(const float4*)(Wrow + k0 + kq * 4);
            unsigned h0, l0, h1, l1;
            bf16split2(v.x, v.y, h0, l0);
            bf16split2(v.z, v.w, h1, l1);
            int base = n * K1_PITCH + 2 * kq;
            sWhi[base] = h0; sWhi[base + 1] = h1;
            sWlo[base] = l0; sWlo[base + 1] = l1;
        }
        __syncthreads();

#pragma unroll
        for (int s = 0; s < 2; s++) {          // two k16 steps per chunk
            // B fragments for all 8 n-tiles
            unsigned bh[8][2], bl[8][2];
#pragma unroll
            for (int n = 0; n < 8; n++) {
                int r = (n * 8 + g) * K1_PITCH + s * 8 + tig;
                bh[n][0] = sWhi[r]; bh[n][1] = sWhi[r + 4];
                bl[n][0] = sWlo[r]; bl[n][1] = sWlo[r + 4];
            }
#pragma unroll
            for (int m = 0; m < 2; m++) {
                int mb = warp * 32 + m * 16;
                int r0 = (mb + g) * K1_PITCH + s * 8 + tig;
                int r1 = (mb + 8 + g) * K1_PITCH + s * 8 + tig;
                unsigned ah[4], al[4];
                ah[0] = sXhi[r0]; ah[1] = sXhi[r1]; ah[2] = sXhi[r0 + 4]; ah[3] = sXhi[r1 + 4];
                al[0] = sXlo[r0]; al[1] = sXlo[r1]; al[2] = sXlo[r0 + 4]; al[3] = sXlo[r1 + 4];
#pragma unroll
                for (int n = 0; n < 8; n++) {
                    mma_bf16(acc[m][n], ah, bh[n]);   // hi*hi
                    mma_bf16(acc[m][n], ah, bl[n]);   // hi*lo
                    mma_bf16(acc[m][n], al, bh[n]);   // lo*hi
                }
            }
        }
    }

    // epilogue: add bias, store.  C[g][2tig..2tig+1], C[g+8][...]
#pragma unroll
    for (int m = 0; m < 2; m++) {
        int r0 = rowBase + warp * 32 + m * 16 + g;
#pragma unroll
        for (int n = 0; n < 8; n++) {
            int col = n * 8 + 2 * tig;
            float b0 = sBias[col], b1 = sBias[col + 1];
            float2 v0 = make_float2(acc[m][n][0] + b0, acc[m][n][1] + b1);
            float2 v1 = make_float2(acc[m][n][2] + b0, acc[m][n][3] + b1);
            *(float2*)(g_G + (size_t)r0 * 64 + col)       = v0;
            *(float2*)(g_G + (size_t)(r0 + 8) * 64 + col) = v1;
        }
    }
}

// ---------------- K2: bi-LSTM scans (both directions) -----------------------
// One warp per block. lane = (b_local 0..3, j 0..7). h exchanged via
// double-buffered shared memory (1 STS + 2 LDS.128 broadcast) instead of 16
// shfls; recurrent dot in ffma2. Gate stream prefetched depth 4.
__global__ void __launch_bounds__(32) k2_bilstm(
    const float* __restrict__ Whhf, const float* __restrict__ Whhb)
{
    __shared__ __align__(16) float hsm[2][4][8];

    const int warpId = blockIdx.x;        // 0..255
    const int lane = threadIdx.x & 31;
    const int dir = warpId >> 7;
    const int wd = warpId & 127;
    const int bl = lane >> 3;             // batch slot in warp
    const int b = (wd << 2) + bl;
    const int j = lane & 7;

    const float* Whh = dir ? Whhb : Whhf;
    float2 wr2[4][4];
#pragma unroll
    for (int g = 0; g < 4; g++)
#pragma unroll
        for (int p = 0; p < 4; p++)
            wr2[g][p] = make_float2(Whh[(g * 8 + j) * 8 + 2 * p],
                                    Whh[(g * 8 + j) * 8 + 2 * p + 1]);

    const int t0 = dir ? 127 : 0;
    const long long stepG = dir ? -(long long)(B_SZ * 64) : (long long)(B_SZ * 64);
    const long long stepH = dir ? -(long long)(B_SZ * 16) : (long long)(B_SZ * 16);
    const float* gp0 = g_G + (size_t)(t0 * B_SZ + b) * 64 + dir * 32 + j;
    float*       hp  = g_h + (size_t)(t0 * B_SZ + b) * 16 + dir * 8 + j;

    float nb[4][4];
#pragma unroll
    for (int p = 0; p < 4; p++) {
        const float* q = gp0 + (long long)p * stepG;
        nb[p][0] = q[0]; nb[p][1] = q[8]; nb[p][2] = q[16]; nb[p][3] = q[24];
    }
    const float* gpf = gp0 + 4 * stepG;

    hsm[0][bl][j] = 0.f;
    __syncwarp();

    float h = 0.f, c = 0.f;
    for (int tt = 0; tt < 128; tt += 4) {
#pragma unroll
        for (int p = 0; p < 4; p++) {
            const int s = tt + p;
            const int ph = s & 1;
            float q0 = nb[p][0], q1 = nb[p][1], q2 = nb[p][2], q3 = nb[p][3];
            if (s < 124) {
                nb[p][0] = gpf[0]; nb[p][1] = gpf[8];
                nb[p][2] = gpf[16]; nb[p][3] = gpf[24];
            }
            gpf += stepG;

            float4 hA = *(const float4*)&hsm[ph][bl][0];
            float4 hB = *(const float4*)&hsm[ph][bl][4];
            float2 hp0 = flo(hA), hp1 = fhi(hA), hp2 = flo(hB), hp3 = fhi(hB);

            float a[4];
#pragma unroll
            for (int g = 0; g < 4; g++) {
                float2 u = ffma2(wr2[g][0], hp0, make_float2(0.f, 0.f));
                float2 v = ffma2(wr2[g][1], hp1, make_float2(0.f, 0.f));
                u = ffma2(wr2[g][2], hp2, u);
                v = ffma2(wr2[g][3], hp3, v);
                a[g] = (u.x + u.y) + (v.x + v.y);
            }
            float ii = sigf(q0 + a[0]), ff = sigf(q1 + a[1]);
            float gg = tanh_fast(q2 + a[2]), oo = sigf(q3 + a[3]);
            c = ff * c + ii * gg;
            h = oo * tanh_fast(c);
            hsm[ph ^ 1][bl][j] = h;
            __syncwarp();
            *hp = h; hp += stepH;
        }
    }
}

// ---------------- K4: ptr-LSTM input projection h @ Wih_p^T + bias ----------
__global__ void __launch_bounds__(256) k4_proj(
    const float* __restrict__ Wp, const float* __restrict__ bihp,
    const float* __restrict__ bhhp)
{
    __shared__ float4 ws4[64][4];
    __shared__ float bs[64];
    const int tid = threadIdx.x;
    if (tid < 64) bs[tid] = bihp[tid] + bhhp[tid];
    {
        float4 v = ((const float4*)Wp)[tid];
        ws4[tid >> 2][tid & 3] = v;
    }
    __syncthreads();

    const int m = blockIdx.x * 256 + tid;
    const float4* hv = (const float4*)(g_h + (size_t)m * 16);
    float4 h0 = hv[0], h1 = hv[1], h2 = hv[2], h3 = hv[3];
    float* gp = g_Gp + (size_t)m * 64;
#pragma unroll
    for (int n4 = 0; n4 < 16; n4++) {
        float4 o;
        float* op = &o.x;
#pragma unroll
        for (int q = 0; q < 4; q++) {
            int n = n4 * 4 + q;
            float4 w0 = ws4[n][0], w1 = ws4[n][1], w2 = ws4[n][2], w3 = ws4[n][3];
            float s = bs[n];
            s += h0.x * w0.x + h0.y * w0.y + h0.z * w0.z + h0.w * w0.w;
            s += h1.x * w1.x + h1.y * w1.y + h1.z * w1.z + h1.w * w1.w;
            s += h2.x * w2.x + h2.y * w2.y + h2.z * w2.z + h2.w * w2.w;
            s += h3.x * w3.x + h3.y * w3.y + h3.z * w3.z + h3.w * w3.w;
            op[q] = s;
        }
        ((float4*)gp)[n4] = o;
    }
}

// ---------------- K5: ptr-LSTM scan (H=16) ----------------------------------
// One warp per block. lane = (b_local 0..1, j 0..15). smem h exchange, ffma2 dot.
__global__ void __launch_bounds__(32) k5_ptr(const float* __restrict__ Whhp)
{
    __shared__ __align__(16) float hsm[2][2][16];

    const int warpId = blockIdx.x;        // 0..255
    const int lane = threadIdx.x & 31;
    const int bl = lane >> 4;
    const int b = (warpId << 1) + bl;
    const int j = lane & 15;

    float2 wr2[4][8];
#pragma unroll
    for (int g = 0; g < 4; g++)
#pragma unroll
        for (int p = 0; p < 8; p++)
            wr2[g][p] = make_float2(Whhp[(g * 16 + j) * 16 + 2 * p],
                                    Whhp[(g * 16 + j) * 16 + 2 * p + 1]);

    const float* gp0 = g_Gp + (size_t)b * 64 + j;
    float*       zp  = g_z  + (size_t)b * 16 + j;
    const long long stepG = (long long)B_SZ * 64;

    float nb[4][4];
#pragma unroll
    for (int p = 0; p < 4; p++) {
        const float* q = gp0 + (long long)p * stepG;
        nb[p][0] = q[0]; nb[p][1] = q[16]; nb[p][2] = q[32]; nb[p][3] = q[48];
    }
    const float* gpf = gp0 + 4 * stepG;

    hsm[0][bl][j] = 0.f;
    __syncwarp();

    float h = 0.f, c = 0.f;
    for (int tt = 0; tt < 128; tt += 4) {
#pragma unroll
        for (int p = 0; p < 4; p++) {
            const int s = tt + p;
            const int ph = s & 1;
            float q0 = nb[p][0], q1 = nb[p][1], q2 = nb[p][2], q3 = nb[p][3];
            if (s < 124) {
                nb[p][0] = gpf[0];  nb[p][1] = gpf[16];
                nb[p][2] = gpf[32]; nb[p][3] = gpf[48];
            }
            gpf += stepG;

            float4 hA = *(const float4*)&hsm[ph][bl][0];
            float4 hB = *(const float4*)&hsm[ph][bl][4];
            float4 hC = *(const float4*)&hsm[ph][bl][8];
            float4 hD = *(const float4*)&hsm[ph][bl][12];
            float2 hq[8] = { flo(hA), fhi(hA), flo(hB), fhi(hB),
                             flo(hC), fhi(hC), flo(hD), fhi(hD) };

            float a[4];
#pragma unroll
            for (int g = 0; g < 4; g++) {
                float2 u = ffma2(wr2[g][0], hq[0], make_float2(0.f, 0.f));
                float2 v = ffma2(wr2[g][1], hq[1], make_float2(0.f, 0.f));
#pragma unroll
                for (int p2 = 1; p2 < 4; p2++) {
                    u = ffma2(wr2[g][2 * p2],     hq[2 * p2],     u);
                    v = ffma2(wr2[g][2 * p2 + 1], hq[2 * p2 + 1], v);
                }
                a[g] = (u.x + u.y) + (v.x + v.y);
            }
            float ii = sigf(q0 + a[0]), ff = sigf(q1 + a[1]);
            float gg = tanh_fast(q2 + a[2]), oo = sigf(q3 + a[3]);
            c = ff * c + ii * gg;
            h = oo * tanh_fast(c);
            hsm[ph ^ 1][bl][j] = h;
            __syncwarp();
            *zp = h; zp += B_SZ * 16;
        }
    }
}

// ---------------- K6: attention + context + scoring epilogue ----------------
__global__ void __launch_bounds__(512) k6_attn(
    const float* __restrict__ Wh, const float* __restrict__ We,
    const float* __restrict__ Wv, float* __restrict__ out)
{
    extern __shared__ float sm[];
    float* hs  = sm;              // 8192
    float* zs  = sm + 8192;       // 8192
    float* rcs = sm + 16384;      // 512
    float* whs = sm + 16896;      // 256
    float* wes = sm + 17152;      // 256
    float* wvs = sm + 17408;      // 16

    const int t = blockIdx.x;
    const int tid = threadIdx.x;

    float4* hs4 = (float4*)hs;
    float4* zs4 = (float4*)zs;
    {
        const float4* hg = (const float4*)(g_h + (size_t)t * B_SZ * 16);
        const float4* zg = (const float4*)(g_z + (size_t)t * B_SZ * 16);
#pragma unroll
        for (int i = 0; i < 4; i++) {
            hs4[tid + i * 512] = hg[tid + i * 512];
            zs4[tid + i * 512] = zg[tid + i * 512];
        }
    }
    if (tid < 256) { whs[tid] = Wh[tid]; wes[tid] = We[tid]; }
    if (tid < 16)  wvs[tid] = Wv[tid];
    __syncthreads();

    // ---- pass A: column sums of exp(S[:,c]), c = tid ----
    {
        const float4* zc = zs4 + tid * 4;
        float4 z0 = zc[0], z1 = zc[1], z2 = zc[2], z3 = zc[3];
        float colsum = 0.f;
        const float4* hp = hs4;
#pragma unroll 4
        for (int b = 0; b < 512; b++) {
            float4 h0 = hp[0], h1 = hp[1], h2 = hp[2], h3 = hp[3];
            hp += 4;
            float2 s2 = make_float2(0.f, 0.f);
            s2 = ffma2(flo(h0), flo(z0), s2); s2 = ffma2(fhi(h0), fhi(z0), s2);
            s2 = ffma2(flo(h1), flo(z1), s2); s2 = ffma2(fhi(h1), fhi(z1), s2);
            s2 = ffma2(flo(h2), flo(z2), s2); s2 = ffma2(fhi(h2), fhi(z2), s2);
            s2 = ffma2(flo(h3), flo(z3), s2); s2 = ffma2(fhi(h3), fhi(z3), s2);
            colsum += __expf(s2.x + s2.y);
        }
        rcs[tid] = 1.0f / colsum;
    }
    __syncthreads();

    // ---- pass B: rows b = tid; recompute S, weight, accumulate ctx ----
    {
        const float4* hb = hs4 + tid * 4;
        float4 b0 = hb[0], b1 = hb[1], b2 = hb[2], b3 = hb[3];
        float2 ctx[8];
#pragma unroll
        for (int q = 0; q < 8; q++) ctx[q] = make_float2(0.f, 0.f);

#pragma unroll 2
        for (int cc = 0; cc < 512; cc++) {
            float4 z0 = zs4[cc * 4 + 0], z1 = zs4[cc * 4 + 1];
            float4 z2 = zs4[cc * 4 + 2], z3 = zs4[cc * 4 + 3];
            float4 h0 = hs4[cc * 4 + 0], h1 = hs4[cc * 4 + 1];
            float4 h2 = hs4[cc * 4 + 2], h3 = hs4[cc * 4 + 3];
            float2 s2 = make_float2(0.f, 0.f);
            s2 = ffma2(flo(b0), flo(z0), s2); s2 = ffma2(fhi(b0), fhi(z0), s2);
            s2 = ffma2(flo(b1), flo(z1), s2); s2 = ffma2(fhi(b1), fhi(z1), s2);
            s2 = ffma2(flo(b2), flo(z2), s2); s2 = ffma2(fhi(b2), fhi(z2), s2);
            s2 = ffma2(flo(b3), flo(z3), s2); s2 = ffma2(fhi(b3), fhi(z3), s2);
            float w = __expf(s2.x + s2.y) * rcs[cc];
            float2 w2 = make_float2(w, w);
            ctx[0] = ffma2(w2, flo(h0), ctx[0]); ctx[1] = ffma2(w2, fhi(h0), ctx[1]);
            ctx[2] = ffma2(w2, flo(h1), ctx[2]); ctx[3] = ffma2(w2, fhi(h1), ctx[3]);
            ctx[4] = ffma2(w2, flo(h2), ctx[4]); ctx[5] = ffma2(w2, fhi(h2), ctx[5]);
            ctx[6] = ffma2(w2, flo(h3), ctx[6]); ctx[7] = ffma2(w2, fhi(h3), ctx[7]);
        }

        float hv[16], cv[16];
        hv[0]=b0.x; hv[1]=b0.y; hv[2]=b0.z; hv[3]=b0.w;
        hv[4]=b1.x; hv[5]=b1.y; hv[6]=b1.z; hv[7]=b1.w;
        hv[8]=b2.x; hv[9]=b2.y; hv[10]=b2.z; hv[11]=b2.w;
        hv[12]=b3.x; hv[13]=b3.y; hv[14]=b3.z; hv[15]=b3.w;
#pragma unroll
        for (int q = 0; q < 8; q++) { cv[2*q] = ctx[q].x; cv[2*q+1] = ctx[q].y; }

        float pacc = 0.f;
#pragma unroll
        for (int d = 0; d < 16; d++) {
            float s = 0.f;
#pragma unroll
            for (int k = 0; k < 16; k++)
                s += hv[k] * whs[d * 16 + k] + cv[k] * wes[d * 16 + k];
            pacc += tanh_fast(s) * wvs[d];
        }
        out[t * B_SZ + tid] = sigf(pacc);
    }
}

// ---------------- launch -----------------------------------------------------
extern "C" void kernel_launch(void* const* d_in, const int* in_sizes, int n_in,
                              void* d_out, int out_size)
{
    const float* x    = (const float*)d_in[0];
    const float* Wihf = (const float*)d_in[1];
    const float* Whhf = (const float*)d_in[2];
    const float* bihf = (const float*)d_in[3];
    const float* bhhf = (const float*)d_in[4];
    const float* Wihb = (const float*)d_in[5];
    const float* Whhb = (const float*)d_in[6];
    const float* bihb = (const float*)d_in[7];
    const float* bhhb = (const float*)d_in[8];
    const float* Wihp = (const float*)d_in[9];
    const float* Whhp = (const float*)d_in[10];
    const float* bihp = (const float*)d_in[11];
    const float* bhhp = (const float*)d_in[12];
    const float* Wh   = (const float*)d_in[13];
    const float* We   = (const float*)d_in[14];
    const float* Wv   = (const float*)d_in[15];
    float* out = (float*)d_out;

    k1_gemm<<<512, 128>>>(x, Wihf, Wihb, bihf, bhhf, bihb, bhhb);
    k2_bilstm<<<256, 32>>>(Whhf, Whhb);
    k4_proj<<<256, 256>>>(Wihp, bihp, bhhp);
    k5_ptr<<<256, 32>>>(Whhp);

    const int smemK6 = (8192 + 8192 + 512 + 256 + 256 + 16) * 4;  // 69696 B
    cudaFuncSetAttribute(k6_attn, cudaFuncAttributeMaxDynamicSharedMemorySize, smemK6);
    k6_attn<<<128, 512, smemK6>>>(Wh, We, Wv, out);
}

// round 7
// speedup vs baseline: 1.7777x; 1.1980x over previous
#include <cuda_runtime.h>
#include <cuda_bf16.h>

#define T_LEN 128
#define B_SZ  512
#define D_IN  768

// ---------------- scratch (device globals; no allocation allowed) ----------
__device__ float g_G [T_LEN * B_SZ * 64];   // bi-LSTM gate preacts (input part + bias)
__device__ float g_h [T_LEN * B_SZ * 16];   // concat bi-LSTM hidden
__device__ float g_Gp[T_LEN * B_SZ * 64];   // ptr-LSTM gate preacts (input part + bias)
__device__ float g_z [T_LEN * B_SZ * 16];   // ptr-LSTM hidden

// ---------------- helpers ---------------------------------------------------
static __device__ __forceinline__ unsigned long long f2u(float2 v) {
    union { float2 f; unsigned long long u; } x; x.f = v; return x.u;
}
static __device__ __forceinline__ float2 u2f(unsigned long long u) {
    union { float2 f; unsigned long long u; } x; x.u = u; return x.f;
}
// packed fp32x2 FMA (B300 FFMA2 — 2x fp32 FMA throughput vs 3-reg FFMA)
static __device__ __forceinline__ float2 ffma2(float2 a, float2 b, float2 c) {
    unsigned long long d;
    asm("fma.rn.f32x2 %0, %1, %2, %3;"
        : "=l"(d) : "l"(f2u(a)), "l"(f2u(b)), "l"(f2u(c)));
    return u2f(d);
}
static __device__ __forceinline__ float2 flo(float4 v) { return make_float2(v.x, v.y); }
static __device__ __forceinline__ float2 fhi(float4 v) { return make_float2(v.z, v.w); }

// HW tanh (MUFU.TANH, sm_75+): single MUFU op, lat~16 vs ~44 for ex2+rcp chain
static __device__ __forceinline__ float tanh_hw(float x) {
    float y;
    asm("tanh.approx.f32 %0, %1;" : "=f"(y) : "f"(x));
    return y;
}
// sigmoid(x) = 0.5*tanh(0.5x) + 0.5  (callers pre-halve x where possible)
static __device__ __forceinline__ float sig_half(float xh) {   // xh = x/2
    return fmaf(0.5f, tanh_hw(xh), 0.5f);
}
static __device__ __forceinline__ float sigf(float x) {
    return fmaf(0.5f, tanh_hw(0.5f * x), 0.5f);
}

// pack two floats into bf16x2 hi part and residual lo part
static __device__ __forceinline__ void bf16split2(float a, float b,
                                                  unsigned& hi, unsigned& lo) {
    __nv_bfloat16 ah = __float2bfloat16_rn(a);
    __nv_bfloat16 bh = __float2bfloat16_rn(b);
    float ar = a - __bfloat162float(ah);
    float br = b - __bfloat162float(bh);
    __nv_bfloat16 al = __float2bfloat16_rn(ar);
    __nv_bfloat16 bl = __float2bfloat16_rn(br);
    hi = (unsigned)__bfloat16_as_ushort(ah) | ((unsigned)__bfloat16_as_ushort(bh) << 16);
    lo = (unsigned)__bfloat16_as_ushort(al) | ((unsigned)__bfloat16_as_ushort(bl) << 16);
}

static __device__ __forceinline__ void mma_bf16(float* d, const unsigned* a,
                                                const unsigned* b) {
    asm volatile(
        "mma.sync.aligned.m16n8k16.row.col.f32.bf16.bf16.f32 "
        "{%0,%1,%2,%3}, {%4,%5,%6,%7}, {%8,%9}, {%0,%1,%2,%3};"
        : "+f"(d[0]), "+f"(d[1]), "+f"(d[2]), "+f"(d[3])
        : "r"(a[0]), "r"(a[1]), "r"(a[2]), "r"(a[3]), "r"(b[0]), "r"(b[1]));
}

// ---------------- K1: x @ [Wih_f;Wih_b]^T + bias -> g_G (bf16x3 tensor) -----
#define K1_PITCH 20
__global__ void __launch_bounds__(128) k1_gemm(
    const float* __restrict__ x,
    const float* __restrict__ Wf, const float* __restrict__ Wb,
    const float* __restrict__ bihf, const float* __restrict__ bhhf,
    const float* __restrict__ bihb, const float* __restrict__ bhhb)
{
    __shared__ unsigned sXhi[128 * K1_PITCH];
    __shared__ unsigned sXlo[128 * K1_PITCH];
    __shared__ unsigned sWhi[64 * K1_PITCH];
    __shared__ unsigned sWlo[64 * K1_PITCH];
    __shared__ float    sBias[64];

    const int tid  = threadIdx.x;
    const int warp = tid >> 5;
    const int lane = tid & 31;
    const int g    = lane >> 2;
    const int tig  = lane & 3;
    const int rowBase = blockIdx.x * 128;

    if (tid < 64)
        sBias[tid] = (tid < 32) ? (bihf[tid] + bhhf[tid])
                                : (bihb[tid - 32] + bhhb[tid - 32]);

    float acc[2][8][4];
#pragma unroll
    for (int m = 0; m < 2; m++)
#pragma unroll
        for (int n = 0; n < 8; n++)
#pragma unroll
            for (int q = 0; q < 4; q++) acc[m][n][q] = 0.f;

    for (int kc = 0; kc < 24; kc++) {
        const int k0 = kc * 32;
        __syncthreads();
#pragma unroll
        for (int i = 0; i < 8; i++) {
            int idx = tid + i * 128;
            int row = idx >> 3, kq = idx & 7;
            float4 v = *(const float4*)(x + (size_t)(rowBase + row) * D_IN + k0 + kq * 4);
            unsigned h0, l0, h1, l1;
            bf16split2(v.x, v.y, h0, l0);
            bf16split2(v.z, v.w, h1, l1);
            int base = row * K1_PITCH + 2 * kq;
            sXhi[base] = h0; sXhi[base + 1] = h1;
            sXlo[base] = l0; sXlo[base + 1] = l1;
        }
#pragma unroll
        for (int i = 0; i < 4; i++) {
            int idx = tid + i * 128;
            int n = idx >> 3, kq = idx & 7;
            const float* Wrow = (n < 32) ? (Wf + n * D_IN) : (Wb + (n - 32) * D_IN);
            float4 v = *(const float4*)(Wrow + k0 + kq * 4);
            unsigned h0, l0, h1, l1;
            bf16split2(v.x, v.y, h0, l0);
            bf16split2(v.z, v.w, h1, l1);
            int base = n * K1_PITCH + 2 * kq;
            sWhi[base] = h0; sWhi[base + 1] = h1;
            sWlo[base] = l0; sWlo[base + 1] = l1;
        }
        __syncthreads();

#pragma unroll
        for (int s = 0; s < 2; s++) {
            unsigned bh[8][2], bl[8][2];
#pragma unroll
            for (int n = 0; n < 8; n++) {
                int r = (n * 8 + g) * K1_PITCH + s * 8 + tig;
                bh[n][0] = sWhi[r]; bh[n][1] = sWhi[r + 4];
                bl[n][0] = sWlo[r]; bl[n][1] = sWlo[r + 4];
            }
#pragma unroll
            for (int m = 0; m < 2; m++) {
                int mb = warp * 32 + m * 16;
                int r0 = (mb + g) * K1_PITCH + s * 8 + tig;
                int r1 = (mb + 8 + g) * K1_PITCH + s * 8 + tig;
                unsigned ah[4], al[4];
                ah[0] = sXhi[r0]; ah[1] = sXhi[r1]; ah[2] = sXhi[r0 + 4]; ah[3] = sXhi[r1 + 4];
                al[0] = sXlo[r0]; al[1] = sXlo[r1]; al[2] = sXlo[r0 + 4]; al[3] = sXlo[r1 + 4];
#pragma unroll
                for (int n = 0; n < 8; n++) {
                    mma_bf16(acc[m][n], ah, bh[n]);
                    mma_bf16(acc[m][n], ah, bl[n]);
                    mma_bf16(acc[m][n], al, bh[n]);
                }
            }
        }
    }

#pragma unroll
    for (int m = 0; m < 2; m++) {
        int r0 = rowBase + warp * 32 + m * 16 + g;
#pragma unroll
        for (int n = 0; n < 8; n++) {
            int col = n * 8 + 2 * tig;
            float b0 = sBias[col], b1 = sBias[col + 1];
            float2 v0 = make_float2(acc[m][n][0] + b0, acc[m][n][1] + b1);
            float2 v1 = make_float2(acc[m][n][2] + b0, acc[m][n][3] + b1);
            *(float2*)(g_G + (size_t)r0 * 64 + col)       = v0;
            *(float2*)(g_G + (size_t)(r0 + 8) * 64 + col) = v1;
        }
    }
}

// ---------------- K2: bi-LSTM scans (both directions) -----------------------
// One warp per block; smem h exchange; HW tanh activations.
// Sigmoid gates (i,f,o): weights+preacts pre-halved so sig = FFMA(0.5,tanh,0.5).
__global__ void __launch_bounds__(32) k2_bilstm(
    const float* __restrict__ Whhf, const float* __restrict__ Whhb)
{
    __shared__ __align__(16) float hsm[2][4][8];

    const int warpId = blockIdx.x;        // 0..255
    const int lane = threadIdx.x & 31;
    const int dir = warpId >> 7;
    const int wd = warpId & 127;
    const int bl = lane >> 3;
    const int b = (wd << 2) + bl;
    const int j = lane & 7;

    const float* Whh = dir ? Whhb : Whhf;
    float2 wr2[4][4];
#pragma unroll
    for (int g = 0; g < 4; g++) {
        const float sc = (g == 2) ? 1.0f : 0.5f;   // halve sigmoid-gate rows
#pragma unroll
        for (int p = 0; p < 4; p++)
            wr2[g][p] = make_float2(sc * Whh[(g * 8 + j) * 8 + 2 * p],
                                    sc * Whh[(g * 8 + j) * 8 + 2 * p + 1]);
    }

    const int t0 = dir ? 127 : 0;
    const long long stepG = dir ? -(long long)(B_SZ * 64) : (long long)(B_SZ * 64);
    const long long stepH = dir ? -(long long)(B_SZ * 16) : (long long)(B_SZ * 16);
    const float* gp0 = g_G + (size_t)(t0 * B_SZ + b) * 64 + dir * 32 + j;
    float*       hp  = g_h + (size_t)(t0 * B_SZ + b) * 16 + dir * 8 + j;

    float nb[4][4];
#pragma unroll
    for (int p = 0; p < 4; p++) {
        const float* q = gp0 + (long long)p * stepG;
        nb[p][0] = 0.5f * q[0]; nb[p][1] = 0.5f * q[8];
        nb[p][2] = q[16];       nb[p][3] = 0.5f * q[24];
    }
    const float* gpf = gp0 + 4 * stepG;

    hsm[0][bl][j] = 0.f;
    __syncwarp();

    float h = 0.f, c = 0.f;
    for (int tt = 0; tt < 128; tt += 4) {
#pragma unroll
        for (int p = 0; p < 4; p++) {
            const int s = tt + p;
            const int ph = s & 1;
            float q0 = nb[p][0], q1 = nb[p][1], q2 = nb[p][2], q3 = nb[p][3];
            if (s < 124) {
                nb[p][0] = 0.5f * gpf[0];  nb[p][1] = 0.5f * gpf[8];
                nb[p][2] = gpf[16];        nb[p][3] = 0.5f * gpf[24];
            }
            gpf += stepG;

            float4 hA = *(const float4*)&hsm[ph][bl][0];
            float4 hB = *(const float4*)&hsm[ph][bl][4];
            float2 hp0 = flo(hA), hp1 = fhi(hA), hp2 = flo(hB), hp3 = fhi(hB);

            float a[4];
#pragma unroll
            for (int g = 0; g < 4; g++) {
                float2 u = ffma2(wr2[g][0], hp0, make_float2(0.f, 0.f));
                float2 v = ffma2(wr2[g][1], hp1, make_float2(0.f, 0.f));
                u = ffma2(wr2[g][2], hp2, u);
                v = ffma2(wr2[g][3], hp3, v);
                a[g] = (u.x + u.y) + (v.x + v.y);
            }
            float ii = sig_half(q0 + a[0]);
            float ff = sig_half(q1 + a[1]);
            float gg = tanh_hw(q2 + a[2]);
            float oo = sig_half(q3 + a[3]);
            c = ff * c + ii * gg;
            h = oo * tanh_hw(c);
            hsm[ph ^ 1][bl][j] = h;
            __syncwarp();
            *hp = h; hp += stepH;
        }
    }
}

// ---------------- K4: ptr-LSTM input projection h @ Wih_p^T + bias ----------
__global__ void __launch_bounds__(256) k4_proj(
    const float* __restrict__ Wp, const float* __restrict__ bihp,
    const float* __restrict__ bhhp)
{
    __shared__ float4 ws4[64][4];
    __shared__ float bs[64];
    const int tid = threadIdx.x;
    if (tid < 64) bs[tid] = bihp[tid] + bhhp[tid];
    {
        float4 v = ((const float4*)Wp)[tid];
        ws4[tid >> 2][tid & 3] = v;
    }
    __syncthreads();

    const int m = blockIdx.x * 256 + tid;
    const float4* hv = (const float4*)(g_h + (size_t)m * 16);
    float4 h0 = hv[0], h1 = hv[1], h2 = hv[2], h3 = hv[3];
    float* gp = g_Gp + (size_t)m * 64;
#pragma unroll
    for (int n4 = 0; n4 < 16; n4++) {
        float4 o;
        float* op = &o.x;
#pragma unroll
        for (int q = 0; q < 4; q++) {
            int n = n4 * 4 + q;
            float4 w0 = ws4[n][0], w1 = ws4[n][1], w2 = ws4[n][2], w3 = ws4[n][3];
            float s = bs[n];
            s += h0.x * w0.x + h0.y * w0.y + h0.z * w0.z + h0.w * w0.w;
            s += h1.x * w1.x + h1.y * w1.y + h1.z * w1.z + h1.w * w1.w;
            s += h2.x * w2.x + h2.y * w2.y + h2.z * w2.z + h2.w * w2.w;
            s += h3.x * w3.x + h3.y * w3.y + h3.z * w3.z + h3.w * w3.w;
            op[q] = s;
        }
        ((float4*)gp)[n4] = o;
    }
}

// ---------------- K5: ptr-LSTM scan (H=16) ----------------------------------
// One warp per block; smem h exchange; HW tanh activations; pre-halved
// sigmoid-gate weights/preacts.
__global__ void __launch_bounds__(32) k5_ptr(const float* __restrict__ Whhp)
{
    __shared__ __align__(16) float hsm[2][2][16];

    const int warpId = blockIdx.x;        // 0..255
    const int lane = threadIdx.x & 31;
    const int bl = lane >> 4;
    const int b = (warpId << 1) + bl;
    const int j = lane & 15;

    float2 wr2[4][8];
#pragma unroll
    for (int g = 0; g < 4; g++) {
        const float sc = (g == 2) ? 1.0f : 0.5f;
#pragma unroll
        for (int p = 0; p < 8; p++)
            wr2[g][p] = make_float2(sc * Whhp[(g * 16 + j) * 16 + 2 * p],
                                    sc * Whhp[(g * 16 + j) * 16 + 2 * p + 1]);
    }

    const float* gp0 = g_Gp + (size_t)b * 64 + j;
    float*       zp  = g_z  + (size_t)b * 16 + j;
    const long long stepG = (long long)B_SZ * 64;

    float nb[4][4];
#pragma unroll
    for (int p = 0; p < 4; p++) {
        const float* q = gp0 + (long long)p * stepG;
        nb[p][0] = 0.5f * q[0];  nb[p][1] = 0.5f * q[16];
        nb[p][2] = q[32];        nb[p][3] = 0.5f * q[48];
    }
    const float* gpf = gp0 + 4 * stepG;

    hsm[0][bl][j] = 0.f;
    __syncwarp();

    float h = 0.f, c = 0.f;
    for (int tt = 0; tt < 128; tt += 4) {
#pragma unroll
        for (int p = 0; p < 4; p++) {
            const int s = tt + p;
            const int ph = s & 1;
            float q0 = nb[p][0], q1 = nb[p][1], q2 = nb[p][2], q3 = nb[p][3];
            if (s < 124) {
                nb[p][0] = 0.5f * gpf[0];   nb[p][1] = 0.5f * gpf[16];
                nb[p][2] = gpf[32];         nb[p][3] = 0.5f * gpf[48];
            }
            gpf += stepG;

            float4 hA = *(const float4*)&hsm[ph][bl][0];
            float4 hB = *(const float4*)&hsm[ph][bl][4];
            float4 hC = *(const float4*)&hsm[ph][bl][8];
            float4 hD = *(const float4*)&hsm[ph][bl][12];
            float2 hq[8] = { flo(hA), fhi(hA), flo(hB), fhi(hB),
                             flo(hC), fhi(hC), flo(hD), fhi(hD) };

            float a[4];
#pragma unroll
            for (int g = 0; g < 4; g++) {
                float2 u = ffma2(wr2[g][0], hq[0], make_float2(0.f, 0.f));
                float2 v = ffma2(wr2[g][1], hq[1], make_float2(0.f, 0.f));
#pragma unroll
                for (int p2 = 1; p2 < 4; p2++) {
                    u = ffma2(wr2[g][2 * p2],     hq[2 * p2],     u);
                    v = ffma2(wr2[g][2 * p2 + 1], hq[2 * p2 + 1], v);
                }
                a[g] = (u.x + u.y) + (v.x + v.y);
            }
            float ii = sig_half(q0 + a[0]);
            float ff = sig_half(q1 + a[1]);
            float gg = tanh_hw(q2 + a[2]);
            float oo = sig_half(q3 + a[3]);
            c = ff * c + ii * gg;
            h = oo * tanh_hw(c);
            hsm[ph ^ 1][bl][j] = h;
            __syncwarp();
            *zp = h; zp += B_SZ * 16;
        }
    }
}

// ---------------- K6: attention + context + scoring epilogue ----------------
__global__ void __launch_bounds__(512) k6_attn(
    const float* __restrict__ Wh, const float* __restrict__ We,
    const float* __restrict__ Wv, float* __restrict__ out)
{
    extern __shared__ float sm[];
    float* hs  = sm;              // 8192
    float* zs  = sm + 8192;       // 8192
    float* rcs = sm + 16384;      // 512
    float* whs = sm + 16896;      // 256
    float* wes = sm + 17152;      // 256
    float* wvs = sm + 17408;      // 16

    const int t = blockIdx.x;
    const int tid = threadIdx.x;

    float4* hs4 = (float4*)hs;
    float4* zs4 = (float4*)zs;
    {
        const float4* hg = (const float4*)(g_h + (size_t)t * B_SZ * 16);
        const float4* zg = (const float4*)(g_z + (size_t)t * B_SZ * 16);
#pragma unroll
        for (int i = 0; i < 4; i++) {
            hs4[tid + i * 512] = hg[tid + i * 512];
            zs4[tid + i * 512] = zg[tid + i * 512];
        }
    }
    if (tid < 256) { whs[tid] = Wh[tid]; wes[tid] = We[tid]; }
    if (tid < 16)  wvs[tid] = Wv[tid];
    __syncthreads();

    // ---- pass A: column sums of exp(S[:,c]), c = tid ----
    {
        const float4* zc = zs4 + tid * 4;
        float4 z0 = zc[0], z1 = zc[1], z2 = zc[2], z3 = zc[3];
        float colsum = 0.f;
        const float4* hp = hs4;
#pragma unroll 4
        for (int b = 0; b < 512; b++) {
            float4 h0 = hp[0], h1 = hp[1], h2 = hp[2], h3 = hp[3];
            hp += 4;
            float2 s2 = make_float2(0.f, 0.f);
            s2 = ffma2(flo(h0), flo(z0), s2); s2 = ffma2(fhi(h0), fhi(z0), s2);
            s2 = ffma2(flo(h1), flo(z1), s2); s2 = ffma2(fhi(h1), fhi(z1), s2);
            s2 = ffma2(flo(h2), flo(z2), s2); s2 = ffma2(fhi(h2), fhi(z2), s2);
            s2 = ffma2(flo(h3), flo(z3), s2); s2 = ffma2(fhi(h3), fhi(z3), s2);
            colsum += __expf(s2.x + s2.y);
        }
        rcs[tid] = 1.0f / colsum;
    }
    __syncthreads();

    // ---- pass B: rows b = tid; recompute S, weight, accumulate ctx ----
    {
        const float4* hb = hs4 + tid * 4;
        float4 b0 = hb[0], b1 = hb[1], b2 = hb[2], b3 = hb[3];
        float2 ctx[8];
#pragma unroll
        for (int q = 0; q < 8; q++) ctx[q] = make_float2(0.f, 0.f);

#pragma unroll 2
        for (int cc = 0; cc < 512; cc++) {
            float4 z0 = zs4[cc * 4 + 0], z1 = zs4[cc * 4 + 1];
            float4 z2 = zs4[cc * 4 + 2], z3 = zs4[cc * 4 + 3];
            float4 h0 = hs4[cc * 4 + 0], h1 = hs4[cc * 4 + 1];
            float4 h2 = hs4[cc * 4 + 2], h3 = hs4[cc * 4 + 3];
            float2 s2 = make_float2(0.f, 0.f);
            s2 = ffma2(flo(b0), flo(z0), s2); s2 = ffma2(fhi(b0), fhi(z0), s2);
            s2 = ffma2(flo(b1), flo(z1), s2); s2 = ffma2(fhi(b1), fhi(z1), s2);
            s2 = ffma2(flo(b2), flo(z2), s2); s2 = ffma2(fhi(b2), fhi(z2), s2);
            s2 = ffma2(flo(b3), flo(z3), s2); s2 = ffma2(fhi(b3), fhi(z3), s2);
            float w = __expf(s2.x + s2.y) * rcs[cc];
            float2 w2 = make_float2(w, w);
            ctx[0] = ffma2(w2, flo(h0), ctx[0]); ctx[1] = ffma2(w2, fhi(h0), ctx[1]);
            ctx[2] = ffma2(w2, flo(h1), ctx[2]); ctx[3] = ffma2(w2, fhi(h1), ctx[3]);
            ctx[4] = ffma2(w2, flo(h2), ctx[4]); ctx[5] = ffma2(w2, fhi(h2), ctx[5]);
            ctx[6] = ffma2(w2, flo(h3), ctx[6]); ctx[7] = ffma2(w2, fhi(h3), ctx[7]);
        }

        float hv[16], cv[16];
        hv[0]=b0.x; hv[1]=b0.y; hv[2]=b0.z; hv[3]=b0.w;
        hv[4]=b1.x; hv[5]=b1.y; hv[6]=b1.z; hv[7]=b1.w;
        hv[8]=b2.x; hv[9]=b2.y; hv[10]=b2.z; hv[11]=b2.w;
        hv[12]=b3.x; hv[13]=b3.y; hv[14]=b3.z; hv[15]=b3.w;
#pragma unroll
        for (int q = 0; q < 8; q++) { cv[2*q] = ctx[q].x; cv[2*q+1] = ctx[q].y; }

        float pacc = 0.f;
#pragma unroll
        for (int d = 0; d < 16; d++) {
            float s = 0.f;
#pragma unroll
            for (int k = 0; k < 16; k++)
                s += hv[k] * whs[d * 16 + k] + cv[k] * wes[d * 16 + k];
            pacc += tanh_hw(s) * wvs[d];
        }
        out[t * B_SZ + tid] = sigf(pacc);
    }
}

// ---------------- launch -----------------------------------------------------
extern "C" void kernel_launch(void* const* d_in, const int* in_sizes, int n_in,
                              void* d_out, int out_size)
{
    const float* x    = (const float*)d_in[0];
    const float* Wihf = (const float*)d_in[1];
    const float* Whhf = (const float*)d_in[2];
    const float* bihf = (const float*)d_in[3];
    const float* bhhf = (const float*)d_in[4];
    const float* Wihb = (const float*)d_in[5];
    const float* Whhb = (const float*)d_in[6];
    const float* bihb = (const float*)d_in[7];
    const float* bhhb = (const float*)d_in[8];
    const float* Wihp = (const float*)d_in[9];
    const float* Whhp = (const float*)d_in[10];
    const float* bihp = (const float*)d_in[11];
    const float* bhhp = (const float*)d_in[12];
    const float* Wh   = (const float*)d_in[13];
    const float* We   = (const float*)d_in[14];
    const float* Wv   = (const float*)d_in[15];
    float* out = (float*)d_out;

    k1_gemm<<<512, 128>>>(x, Wihf, Wihb, bihf, bhhf, bihb, bhhb);
    k2_bilstm<<<256, 32>>>(Whhf, Whhb);
    k4_proj<<<256, 256>>>(Wihp, bihp, bhhp);
    k5_ptr<<<256, 32>>>(Whhp);

    const int smemK6 = (8192 + 8192 + 512 + 256 + 256 + 16) * 4;  // 69696 B
    cudaFuncSetAttribute(k6_attn, cudaFuncAttributeMaxDynamicSharedMemorySize, smemK6);
    k6_attn<<<128, 512, smemK6>>>(Wh, We, Wv, out);
}